// round 10
// baseline (speedup 1.0000x reference)
#include <cuda_runtime.h>
#include <cuda_bf16.h>
#include <mma.h>
#include <math.h>

using namespace nvcuda;
typedef __nv_bfloat16 bf16;

// ---------------------------------------------------------------------------
// B=256, RANK=512, R4=128, R2=256
// conv1   GEMM: Y[b][n]              = latent @ W1cat  M=256  N=5632 K=256
// convT16 GEMM: Z[(b*16+s2)][(co,k)] = X2 @ W2         M=4096 N=4096 K=128
// convT2  GEMM: Z[(b*32+t)][(co,k)]  = X3 @ W3         M=8192 N=1024 K=256
// All bf16x3 (hi*hi + hi*lo + lo*hi, fp32 accumulate).
// GEMM mainloops are register-prefetch pipelined (LDG of next K-chunk issued
// before the current chunk's MMAs).
// ---------------------------------------------------------------------------

__device__ __align__(16) bf16 g_lathi[256 * 256];      // [b][ci]
__device__ __align__(16) bf16 g_latlo[256 * 256];
__device__ __align__(16) bf16 g_w1hi[256 * 5632];      // [ci][n]  c|h|w concat
__device__ __align__(16) bf16 g_w1lo[256 * 5632];
__device__ float g_bias1[5632];
__device__ float g_craw[256 * 1536];                   // conv1 c raw (bias incl)
__device__ float g_x2raw[2][4096 * 128];               // [(b,s2)][ci] raw
__device__ float g_p1sum[4][5632];
__device__ float g_p1sq [4][5632];
__device__ float g_sc1c[512], g_sh1c[512];
__device__ float g_sc1[2 * 128], g_sh1[2 * 128];       // h/w BN1 per ci
__device__ __align__(16) bf16 g_w2hi[2][128 * 4096];
__device__ __align__(16) bf16 g_w2lo[2][128 * 4096];
__device__ __align__(16) bf16 g_w3hi[2][256 * 1024];
__device__ __align__(16) bf16 g_w3lo[2][256 * 1024];
__device__ float g_y2t[2][8192 * 256];                 // raw conv2 out, gemm2-A layout
__device__ float g_psum[2 * 256 * 256];
__device__ float g_psq [2 * 256 * 256];
__device__ float g_sc[2 * 256];
__device__ float g_sh[2 * 256];
__device__ float g_o3[2 * 256 * 512 * 32];             // [s][b][r][32]

__device__ __forceinline__ void bf16split(float x, bf16& h, bf16& l) {
    h = __float2bfloat16(x);
    l = __float2bfloat16(x - __bfloat162float(h));
}

constexpr int ALD = 40;
constexpr int BLD = 136;
constexpr int ZLD = 132;
constexpr int A_ELEMS = 128 * ALD;
constexpr int B_ELEMS = 32 * BLD;
constexpr int SM_G16_B = 128 * ZLD * 4;                    // 67584
constexpr int SM_G2_B  = 128 * ZLD * 4 + 256 * 36 * 4;     // 104448

__device__ __forceinline__ void reduce2_256(float& s, float& ss) {
    __shared__ float rs[8], rss[8];
    #pragma unroll
    for (int o = 16; o > 0; o >>= 1) {
        s  += __shfl_down_sync(0xffffffffu, s,  o);
        ss += __shfl_down_sync(0xffffffffu, ss, o);
    }
    int wid = threadIdx.x >> 5, lane = threadIdx.x & 31;
    if (lane == 0) { rs[wid] = s; rss[wid] = ss; }
    __syncthreads();
    if (threadIdx.x < 32) {
        float a = lane < 8 ? rs[lane] : 0.f;
        float b = lane < 8 ? rss[lane] : 0.f;
        #pragma unroll
        for (int o = 4; o > 0; o >>= 1) {
            a += __shfl_down_sync(0xffffffffu, a, o);
            b += __shfl_down_sync(0xffffffffu, b, o);
        }
        if (lane == 0) { rs[0] = a; rss[0] = b; }
    }
    __syncthreads();
    s = rs[0]; ss = rss[0];
}

// ---------------------------------------------------------------------------
// bf16x3 128x128 block GEMM core (A/B bf16 in gmem), reg-prefetch pipelined.
// ---------------------------------------------------------------------------
template<int KTOT>
__device__ __forceinline__ void gemm_bf16x3(
    const bf16* __restrict__ Ahi, const bf16* __restrict__ Alo,
    const bf16* __restrict__ Bhi, const bf16* __restrict__ Blo,
    int m0, int n0, int ldb, char* smraw, float* Zt)
{
    bf16* sAh = (bf16*)smraw;
    bf16* sAl = sAh + A_ELEMS;
    bf16* sBh = sAl + A_ELEMS;
    bf16* sBl = sBh + B_ELEMS;
    int tid = threadIdx.x, w = tid >> 5;
    int mw = w >> 1, nw = w & 1;
    int arow = tid >> 2, aseg = (tid & 3) * 8;
    int brow = tid >> 4, bseg = (tid & 15) * 8;

    wmma::fragment<wmma::accumulator, 16, 16, 16, float> c[2][4];
    #pragma unroll
    for (int i = 0; i < 2; i++)
        #pragma unroll
        for (int j = 0; j < 4; j++) wmma::fill_fragment(c[i][j], 0.f);

    uint4 rAh[2], rAl[2], rBh[2], rBl[2];
    #pragma unroll
    for (int r = 0; r < 2; r++) {
        int row = arow + 64 * r;
        rAh[r] = *(const uint4*)(Ahi + (size_t)(m0 + row) * KTOT + aseg);
        rAl[r] = *(const uint4*)(Alo + (size_t)(m0 + row) * KTOT + aseg);
    }
    #pragma unroll
    for (int r = 0; r < 2; r++) {
        int row = brow + 16 * r;
        rBh[r] = *(const uint4*)(Bhi + (size_t)row * ldb + n0 + bseg);
        rBl[r] = *(const uint4*)(Blo + (size_t)row * ldb + n0 + bseg);
    }

    for (int kc = 0; kc < KTOT; kc += 32) {
        #pragma unroll
        for (int r = 0; r < 2; r++) {
            int row = arow + 64 * r;
            *(uint4*)(sAh + row * ALD + aseg) = rAh[r];
            *(uint4*)(sAl + row * ALD + aseg) = rAl[r];
        }
        #pragma unroll
        for (int r = 0; r < 2; r++) {
            int row = brow + 16 * r;
            *(uint4*)(sBh + row * BLD + bseg) = rBh[r];
            *(uint4*)(sBl + row * BLD + bseg) = rBl[r];
        }
        __syncthreads();
        if (kc + 32 < KTOT) {                      // prefetch next chunk
            int kn = kc + 32;
            #pragma unroll
            for (int r = 0; r < 2; r++) {
                int row = arow + 64 * r;
                rAh[r] = *(const uint4*)(Ahi + (size_t)(m0 + row) * KTOT + kn + aseg);
                rAl[r] = *(const uint4*)(Alo + (size_t)(m0 + row) * KTOT + kn + aseg);
            }
            #pragma unroll
            for (int r = 0; r < 2; r++) {
                int row = brow + 16 * r;
                rBh[r] = *(const uint4*)(Bhi + (size_t)(kn + row) * ldb + n0 + bseg);
                rBl[r] = *(const uint4*)(Blo + (size_t)(kn + row) * ldb + n0 + bseg);
            }
        }
        #pragma unroll
        for (int k0 = 0; k0 < 32; k0 += 16) {
            wmma::fragment<wmma::matrix_a, 16, 16, 16, bf16, wmma::row_major> ah[2], al[2];
            #pragma unroll
            for (int i = 0; i < 2; i++) {
                wmma::load_matrix_sync(ah[i], sAh + (mw * 32 + i * 16) * ALD + k0, ALD);
                wmma::load_matrix_sync(al[i], sAl + (mw * 32 + i * 16) * ALD + k0, ALD);
            }
            #pragma unroll
            for (int j = 0; j < 4; j++) {
                wmma::fragment<wmma::matrix_b, 16, 16, 16, bf16, wmma::row_major> bh, bl;
                wmma::load_matrix_sync(bh, sBh + k0 * BLD + nw * 64 + j * 16, BLD);
                wmma::load_matrix_sync(bl, sBl + k0 * BLD + nw * 64 + j * 16, BLD);
                #pragma unroll
                for (int i = 0; i < 2; i++) {
                    wmma::mma_sync(c[i][j], ah[i], bh, c[i][j]);
                    wmma::mma_sync(c[i][j], ah[i], bl, c[i][j]);
                    wmma::mma_sync(c[i][j], al[i], bh, c[i][j]);
                }
            }
        }
        __syncthreads();
    }
    #pragma unroll
    for (int i = 0; i < 2; i++)
        #pragma unroll
        for (int j = 0; j < 4; j++)
            wmma::store_matrix_sync(Zt + (mw * 32 + i * 16) * ZLD + nw * 64 + j * 16,
                                    c[i][j], ZLD, wmma::mem_row_major);
    __syncthreads();
}

// ---------------------------------------------------------------------------
// Stage 0: ALL weight prep in one launch. grid 11798 x 256.
// ---------------------------------------------------------------------------
__global__ void k_wprep(const float* __restrict__ cW1, const float* __restrict__ hW1,
                        const float* __restrict__ wW1,
                        const float* __restrict__ cB,  const float* __restrict__ hB,
                        const float* __restrict__ wB,
                        const float* __restrict__ hW2, const float* __restrict__ wW2,
                        const float* __restrict__ hW3, const float* __restrict__ wW3) {
    int blk = blockIdx.x, tid = threadIdx.x;
    if (blk < 5632) {
        int i = blk * 256 + tid;
        int ci = i / 5632, n = i % 5632;
        float x;
        if (n < 1536)      x = cW1[ci * 1536 + n];
        else if (n < 3584) x = hW1[ci * 2048 + n - 1536];
        else               x = wW1[ci * 2048 + n - 3584];
        bf16 h, l; bf16split(x, h, l);
        g_w1hi[i] = h; g_w1lo[i] = l;
    } else if (blk < 9728) {
        int i = (blk - 5632) * 256 + tid;
        int s_ = i >= 524288;
        int j = i - s_ * 524288;
        bf16 h, l; bf16split((s_ ? wW2 : hW2)[j], h, l);
        g_w2hi[s_][j] = h; g_w2lo[s_][j] = l;
    } else if (blk < 11776) {
        int i = (blk - 9728) * 256 + tid;
        int s_ = i >= 262144;
        int j = i - s_ * 262144;
        bf16 h, l; bf16split((s_ ? wW3 : hW3)[j], h, l);
        g_w3hi[s_][j] = h; g_w3lo[s_][j] = l;
    } else {
        int n = (blk - 11776) * 256 + tid;
        if (n < 5632) {
            float v;
            if (n < 1536)      v = cB[n / 3];
            else if (n < 3584) v = hB[(n - 1536) >> 4];
            else               v = wB[(n - 3584) >> 4];
            g_bias1[n] = v;
        }
    }
}

// ---------------------------------------------------------------------------
// Stage 1: latent row b -> bf16 hi/lo [b][ci].
// ---------------------------------------------------------------------------
__global__ void k_latent(const float* __restrict__ noise, const int* __restrict__ label,
                         const float* __restrict__ lin_w, const float* __restrict__ lin_b,
                         const float* __restrict__ g,     const float* __restrict__ be,
                         const float* __restrict__ emb) {
    int j = blockIdx.x, b = threadIdx.x;
    if (j >= 128) {
        int jj = j - 128;
        bf16 h, l;
        bf16split(emb[label[b] * 128 + jj], h, l);
        g_lathi[b * 256 + 128 + jj] = h;
        g_latlo[b * 256 + 128 + jj] = l;
        return;
    }
    __shared__ float wsm[100];
    if (b < 100) wsm[b] = lin_w[j * 100 + b];
    __syncthreads();
    float acc = lin_b[j];
    const float* nb = noise + b * 100;
    #pragma unroll 4
    for (int i = 0; i < 100; i++) acc += nb[i] * wsm[i];
    float s = acc, ss = acc * acc;
    reduce2_256(s, ss);
    float mean = s * (1.f / 256.f);
    float var  = ss * (1.f / 256.f) - mean * mean;
    float sc   = g[j] * rsqrtf(var + 1e-5f);
    float v    = (acc - mean) * sc + be[j];
    v = v >= 0.f ? v : 0.01f * v;
    bf16 h, l;
    bf16split(v, h, l);
    g_lathi[b * 256 + j] = h;
    g_latlo[b * 256 + j] = l;
}

// ---------------------------------------------------------------------------
// Stage 2: conv1 GEMM. grid (44, 2). Epilogue: +bias, raw out, col partials.
// ---------------------------------------------------------------------------
__global__ void __launch_bounds__(256)
k_gemm1() {
    extern __shared__ char smraw[];
    float* Zt = (float*)smraw;
    int n0 = blockIdx.x * 128, m0 = blockIdx.y * 128;
    gemm_bf16x3<256>(g_lathi, g_latlo, g_w1hi, g_w1lo, m0, n0, 5632, smraw, Zt);

    __shared__ float sbias[128];
    int tid = threadIdx.x;
    if (tid < 128) sbias[tid] = g_bias1[n0 + tid];
    __syncthreads();

    if (n0 < 1536) {
        for (int r = 0; r < 64; r++) {
            int i = tid + 256 * r;
            int row = i >> 7, col = i & 127;
            float y = Zt[row * ZLD + col] + sbias[col];
            Zt[row * ZLD + col] = y;
            g_craw[(m0 + row) * 1536 + n0 + col] = y;
        }
    } else {
        int s_ = n0 >= 3584;
        int cobase = (n0 - (s_ ? 3584 : 1536)) >> 4;
        for (int r = 0; r < 64; r++) {
            int i = tid + 256 * r;
            int row = i >> 7, col = i & 127;
            float y = Zt[row * ZLD + col] + sbias[col];
            Zt[row * ZLD + col] = y;
            int k = col & 15, co = cobase + (col >> 4);
            g_x2raw[s_][((m0 + row) * 16 + k) * 128 + co] = y;
        }
    }
    __syncthreads();
    int col = tid & 127, half = tid >> 7;
    float sum = 0.f, sq = 0.f;
    for (int r = 0; r < 64; r++) {
        float y = Zt[(half * 64 + r) * ZLD + col];
        sum += y;
        sq  += y * y;
    }
    int p = blockIdx.y * 2 + half;
    g_p1sum[p][n0 + col] = sum;
    g_p1sq [p][n0 + col] = sq;
}

// ---------------------------------------------------------------------------
// Stage 2b: conv1 BN stats. grid 12 x 256 — one (co, part) per thread,
// width-4 shfl fold.
// ---------------------------------------------------------------------------
__global__ void __launch_bounds__(256)
k_bnstat1(const float* __restrict__ cG, const float* __restrict__ cBe,
          const float* __restrict__ hG, const float* __restrict__ hBe,
          const float* __restrict__ wG, const float* __restrict__ wBe) {
    int gid = blockIdx.x * 256 + threadIdx.x;
    if (gid < 2048) {                                  // c branch: 512 co x 4 p
        int co = gid >> 2, p = gid & 3;
        const float* ps = g_p1sum[p] + co * 3;
        const float* pq = g_p1sq [p] + co * 3;
        float sum = ps[0] + ps[1] + ps[2];
        float sq  = pq[0] + pq[1] + pq[2];
        sum += __shfl_down_sync(0xffffffffu, sum, 2, 4);
        sum += __shfl_down_sync(0xffffffffu, sum, 1, 4);
        sq  += __shfl_down_sync(0xffffffffu, sq,  2, 4);
        sq  += __shfl_down_sync(0xffffffffu, sq,  1, 4);
        if (p == 0) {
            const float invN = 1.f / 768.f;
            float mean = sum * invN, var = sq * invN - mean * mean;
            float sc = cG[co] * rsqrtf(var + 1e-5f);
            g_sc1c[co] = sc;
            g_sh1c[co] = cBe[co] - mean * sc;
        }
    } else {                                           // h/w: 256 co x 4 p
        int id = gid - 2048;
        int coidx = id >> 2, p = id & 3;
        int s_ = coidx >> 7, co = coidx & 127;
        int base = 1536 + s_ * 2048 + co * 16;
        const float4* ps = (const float4*)(g_p1sum[p] + base);
        const float4* pq = (const float4*)(g_p1sq [p] + base);
        float sum = 0.f, sq = 0.f;
        #pragma unroll
        for (int i = 0; i < 4; i++) {
            float4 v = ps[i]; sum += v.x + v.y + v.z + v.w;
            float4 q = pq[i]; sq  += q.x + q.y + q.z + q.w;
        }
        sum += __shfl_down_sync(0xffffffffu, sum, 2, 4);
        sum += __shfl_down_sync(0xffffffffu, sum, 1, 4);
        sq  += __shfl_down_sync(0xffffffffu, sq,  2, 4);
        sq  += __shfl_down_sync(0xffffffffu, sq,  1, 4);
        if (p == 0) {
            const float* G  = s_ ? wG  : hG;
            const float* Be = s_ ? wBe : hBe;
            const float invN = 1.f / 4096.f;
            float mean = sum * invN, var = sq * invN - mean * mean;
            float sc = G[co] * rsqrtf(var + 1e-5f);
            g_sc1[s_ * 128 + co] = sc;
            g_sh1[s_ * 128 + co] = Be[co] - mean * sc;
        }
    }
}

// ---------------------------------------------------------------------------
// Stage 3: convT16 GEMM (pipelined), BN1 fused in A loader; epilogue folds +
// writes raw y2 in gemm2-A layout + BN2 partials. grid (32,32,2).
// ---------------------------------------------------------------------------
__global__ void __launch_bounds__(256)
k_gemm16(const float* __restrict__ hB2, const float* __restrict__ wB2) {
    extern __shared__ char smraw[];
    float* Zt = (float*)smraw;
    bf16* sAh = (bf16*)smraw;
    bf16* sAl = sAh + A_ELEMS;
    bf16* sBh = sAl + A_ELEMS;
    bf16* sBl = sBh + B_ELEMS;
    __shared__ float ssc[128], ssh[128];
    int s_ = blockIdx.z;
    int m0 = blockIdx.y * 128, n0 = blockIdx.x * 128;
    int tid = threadIdx.x, w = tid >> 5, mw = w >> 1, nw = w & 1;
    int arow = tid >> 2, aseg = (tid & 3) * 8;
    int brow = tid >> 4, bseg = (tid & 15) * 8;
    if (tid < 128) {
        ssc[tid] = g_sc1[s_ * 128 + tid];
        ssh[tid] = g_sh1[s_ * 128 + tid];
    }
    const bf16* Bhi = g_w2hi[s_];
    const bf16* Blo = g_w2lo[s_];
    const float* Xr = g_x2raw[s_];

    wmma::fragment<wmma::accumulator, 16, 16, 16, float> c[2][4];
    #pragma unroll
    for (int i = 0; i < 2; i++)
        #pragma unroll
        for (int j = 0; j < 4; j++) wmma::fill_fragment(c[i][j], 0.f);

    float4 rA[2][2];
    uint4 rBh[2], rBl[2];
    #pragma unroll
    for (int r = 0; r < 2; r++) {
        const float* src = Xr + (size_t)(m0 + arow + 64 * r) * 128 + aseg;
        rA[r][0] = *(const float4*)src;
        rA[r][1] = *(const float4*)(src + 4);
    }
    #pragma unroll
    for (int r = 0; r < 2; r++) {
        int row = brow + 16 * r;
        rBh[r] = *(const uint4*)(Bhi + (size_t)row * 4096 + n0 + bseg);
        rBl[r] = *(const uint4*)(Blo + (size_t)row * 4096 + n0 + bseg);
    }
    __syncthreads();                                  // ssc/ssh visible

    for (int kc = 0; kc < 128; kc += 32) {
        #pragma unroll
        for (int r = 0; r < 2; r++) {                 // A: BN + lrelu + split
            int row = arow + 64 * r;
            float vs[8] = {rA[r][0].x, rA[r][0].y, rA[r][0].z, rA[r][0].w,
                           rA[r][1].x, rA[r][1].y, rA[r][1].z, rA[r][1].w};
            __align__(16) bf16 hs[8], ls[8];
            #pragma unroll
            for (int j = 0; j < 8; j++) {
                int ci = kc + aseg + j;
                float y = vs[j] * ssc[ci] + ssh[ci];
                y = y >= 0.f ? y : 0.2f * y;
                bf16split(y, hs[j], ls[j]);
            }
            *(uint4*)(sAh + row * ALD + aseg) = *(uint4*)hs;
            *(uint4*)(sAl + row * ALD + aseg) = *(uint4*)ls;
        }
        #pragma unroll
        for (int r = 0; r < 2; r++) {
            int row = brow + 16 * r;
            *(uint4*)(sBh + row * BLD + bseg) = rBh[r];
            *(uint4*)(sBl + row * BLD + bseg) = rBl[r];
        }
        __syncthreads();
        if (kc + 32 < 128) {
            int kn = kc + 32;
            #pragma unroll
            for (int r = 0; r < 2; r++) {
                const float* src = Xr + (size_t)(m0 + arow + 64 * r) * 128 + kn + aseg;
                rA[r][0] = *(const float4*)src;
                rA[r][1] = *(const float4*)(src + 4);
            }
            #pragma unroll
            for (int r = 0; r < 2; r++) {
                int row = brow + 16 * r;
                rBh[r] = *(const uint4*)(Bhi + (size_t)(kn + row) * 4096 + n0 + bseg);
                rBl[r] = *(const uint4*)(Blo + (size_t)(kn + row) * 4096 + n0 + bseg);
            }
        }
        #pragma unroll
        for (int k0 = 0; k0 < 32; k0 += 16) {
            wmma::fragment<wmma::matrix_a, 16, 16, 16, bf16, wmma::row_major> ah[2], al[2];
            #pragma unroll
            for (int i = 0; i < 2; i++) {
                wmma::load_matrix_sync(ah[i], sAh + (mw * 32 + i * 16) * ALD + k0, ALD);
                wmma::load_matrix_sync(al[i], sAl + (mw * 32 + i * 16) * ALD + k0, ALD);
            }
            #pragma unroll
            for (int j = 0; j < 4; j++) {
                wmma::fragment<wmma::matrix_b, 16, 16, 16, bf16, wmma::row_major> bh, bl;
                wmma::load_matrix_sync(bh, sBh + k0 * BLD + nw * 64 + j * 16, BLD);
                wmma::load_matrix_sync(bl, sBl + k0 * BLD + nw * 64 + j * 16, BLD);
                #pragma unroll
                for (int i = 0; i < 2; i++) {
                    wmma::mma_sync(c[i][j], ah[i], bh, c[i][j]);
                    wmma::mma_sync(c[i][j], ah[i], bl, c[i][j]);
                    wmma::mma_sync(c[i][j], al[i], bh, c[i][j]);
                }
            }
        }
        __syncthreads();
    }
    #pragma unroll
    for (int i = 0; i < 2; i++)
        #pragma unroll
        for (int j = 0; j < 4; j++)
            wmma::store_matrix_sync(Zt + (mw * 32 + i * 16) * ZLD + nw * 64 + j * 16,
                                    c[i][j], ZLD, wmma::mem_row_major);
    __syncthreads();

    // fold epilogue -> g_y2t[(b*32+t)][co]
    const float* Bi = s_ ? wB2 : hB2;
    int pair = tid >> 2, sub = tid & 3;
    int bb = pair >> 3, cc = pair & 7;
    int b  = blockIdx.y * 8 + bb;
    int co = blockIdx.x * 8 + cc;
    float bias = Bi[co];
    float psum = 0.f, psq = 0.f;
    float* yo = g_y2t[s_] + (size_t)b * 32 * 256 + co;
    const float* zrow = Zt + (bb * 16) * ZLD + cc * 16;
    #pragma unroll
    for (int ti = 0; ti < 8; ti++) {
        int t = sub + ti * 4;
        float v = 0.f;
        if (t < 31) {
            #pragma unroll
            for (int k = 0; k < 16; k++) {
                int s2 = t - k;
                if (s2 >= 0 && s2 < 16) v += zrow[s2 * ZLD + k];
            }
            v += bias;
        }
        yo[t * 256] = v;
        psum += v;
        psq  += v * v;
    }
    psum += __shfl_down_sync(0xffffffffu, psum, 2, 4);
    psum += __shfl_down_sync(0xffffffffu, psum, 1, 4);
    psq  += __shfl_down_sync(0xffffffffu, psq, 2, 4);
    psq  += __shfl_down_sync(0xffffffffu, psq, 1, 4);
    if (sub == 0) {
        g_psum[s_ * 65536 + b * 256 + co] = psum;
        g_psq [s_ * 65536 + b * 256 + co] = psq;
    }
}

// ---------------------------------------------------------------------------
// Stage 3b: BN2 partial reduce. grid 16 x 256.
// ---------------------------------------------------------------------------
__global__ void __launch_bounds__(256)
k_bnstat(const float* __restrict__ hG, const float* __restrict__ hBe,
         const float* __restrict__ wG, const float* __restrict__ wBe) {
    int s_  = blockIdx.x >> 3;
    int co0 = (blockIdx.x & 7) * 32;
    int col = threadIdx.x & 31, bp = threadIdx.x >> 5;
    const float* ps = g_psum + s_ * 65536 + co0 + col;
    const float* pq = g_psq  + s_ * 65536 + co0 + col;
    float sum = 0.f, sq = 0.f;
    #pragma unroll 8
    for (int i = 0; i < 32; i++) {
        int b = bp + 8 * i;
        sum += ps[b * 256];
        sq  += pq[b * 256];
    }
    __shared__ float ssum[8][32], ssq[8][32];
    ssum[bp][col] = sum; ssq[bp][col] = sq;
    __syncthreads();
    if (bp == 0) {
        #pragma unroll
        for (int r = 1; r < 8; r++) { sum += ssum[r][col]; sq += ssq[r][col]; }
        const float* G  = s_ ? wG  : hG;
        const float* Be = s_ ? wBe : hBe;
        int co = co0 + col;
        const float invN = 1.f / (256.f * 31.f);
        float mean = sum * invN, var = sq * invN - mean * mean;
        float sc = G[co] * rsqrtf(var + 1e-5f);
        g_sc[s_ * 256 + co] = sc;
        g_sh[s_ * 256 + co] = Be[co] - mean * sc;
    }
}

// ---------------------------------------------------------------------------
// Stage 4: convT2 GEMM (pipelined), BN2+lrelu+split fused in A loader;
// epilogue folds k=2 + tanh + coalesced store. grid (8,64,2).
// ---------------------------------------------------------------------------
__global__ void __launch_bounds__(256)
k_gemm2(const float* __restrict__ hB3, const float* __restrict__ wB3) {
    extern __shared__ char smraw[];
    float* Zt = (float*)smraw;
    bf16* sAh = (bf16*)smraw;
    bf16* sAl = sAh + A_ELEMS;
    bf16* sBh = sAl + A_ELEMS;
    bf16* sBl = sBh + B_ELEMS;
    __shared__ float ssc[256], ssh[256];
    int s_ = blockIdx.z;
    int m0 = blockIdx.y * 128, n0 = blockIdx.x * 128;
    int tid = threadIdx.x, w = tid >> 5, mw = w >> 1, nw = w & 1;
    int arow = tid >> 2, aseg = (tid & 3) * 8;
    int brow = tid >> 4, bseg = (tid & 15) * 8;
    ssc[tid] = g_sc[s_ * 256 + tid];
    ssh[tid] = g_sh[s_ * 256 + tid];
    const bf16* Bhi = g_w3hi[s_];
    const bf16* Blo = g_w3lo[s_];
    const float* Xr = g_y2t[s_];

    wmma::fragment<wmma::accumulator, 16, 16, 16, float> c[2][4];
    #pragma unroll
    for (int i = 0; i < 2; i++)
        #pragma unroll
        for (int j = 0; j < 4; j++) wmma::fill_fragment(c[i][j], 0.f);

    float4 rA[2][2];
    uint4 rBh[2], rBl[2];
    #pragma unroll
    for (int r = 0; r < 2; r++) {
        const float* src = Xr + (size_t)(m0 + arow + 64 * r) * 256 + aseg;
        rA[r][0] = *(const float4*)src;
        rA[r][1] = *(const float4*)(src + 4);
    }
    #pragma unroll
    for (int r = 0; r < 2; r++) {
        int row = brow + 16 * r;
        rBh[r] = *(const uint4*)(Bhi + (size_t)row * 1024 + n0 + bseg);
        rBl[r] = *(const uint4*)(Blo + (size_t)row * 1024 + n0 + bseg);
    }
    __syncthreads();                                  // ssc/ssh visible

    for (int kc = 0; kc < 256; kc += 32) {
        #pragma unroll
        for (int r = 0; r < 2; r++) {
            int row = arow + 64 * r;
            bool zero = (row & 31) == 31;             // t==31 rows are zero input
            float vs[8] = {rA[r][0].x, rA[r][0].y, rA[r][0].z, rA[r][0].w,
                           rA[r][1].x, rA[r][1].y, rA[r][1].z, rA[r][1].w};
            __align__(16) bf16 hs[8], ls[8];
            #pragma unroll
            for (int j = 0; j < 8; j++) {
                int ci = kc + aseg + j;
                float y = vs[j] * ssc[ci] + ssh[ci];
                y = y >= 0.f ? y : 0.2f * y;
                if (zero) y = 0.f;
                bf16split(y, hs[j], ls[j]);
            }
            *(uint4*)(sAh + row * ALD + aseg) = *(uint4*)hs;
            *(uint4*)(sAl + row * ALD + aseg) = *(uint4*)ls;
        }
        #pragma unroll
        for (int r = 0; r < 2; r++) {
            int row = brow + 16 * r;
            *(uint4*)(sBh + row * BLD + bseg) = rBh[r];
            *(uint4*)(sBl + row * BLD + bseg) = rBl[r];
        }
        __syncthreads();
        if (kc + 32 < 256) {
            int kn = kc + 32;
            #pragma unroll
            for (int r = 0; r < 2; r++) {
                const float* src = Xr + (size_t)(m0 + arow + 64 * r) * 256 + kn + aseg;
                rA[r][0] = *(const float4*)src;
                rA[r][1] = *(const float4*)(src + 4);
            }
            #pragma unroll
            for (int r = 0; r < 2; r++) {
                int row = brow + 16 * r;
                rBh[r] = *(const uint4*)(Bhi + (size_t)(kn + row) * 1024 + n0 + bseg);
                rBl[r] = *(const uint4*)(Blo + (size_t)(kn + row) * 1024 + n0 + bseg);
            }
        }
        #pragma unroll
        for (int k0 = 0; k0 < 32; k0 += 16) {
            wmma::fragment<wmma::matrix_a, 16, 16, 16, bf16, wmma::row_major> ah[2], al[2];
            #pragma unroll
            for (int i = 0; i < 2; i++) {
                wmma::load_matrix_sync(ah[i], sAh + (mw * 32 + i * 16) * ALD + k0, ALD);
                wmma::load_matrix_sync(al[i], sAl + (mw * 32 + i * 16) * ALD + k0, ALD);
            }
            #pragma unroll
            for (int j = 0; j < 4; j++) {
                wmma::fragment<wmma::matrix_b, 16, 16, 16, bf16, wmma::row_major> bh, bl;
                wmma::load_matrix_sync(bh, sBh + k0 * BLD + nw * 64 + j * 16, BLD);
                wmma::load_matrix_sync(bl, sBl + k0 * BLD + nw * 64 + j * 16, BLD);
                #pragma unroll
                for (int i = 0; i < 2; i++) {
                    wmma::mma_sync(c[i][j], ah[i], bh, c[i][j]);
                    wmma::mma_sync(c[i][j], ah[i], bl, c[i][j]);
                    wmma::mma_sync(c[i][j], al[i], bh, c[i][j]);
                }
            }
        }
        __syncthreads();
    }
    #pragma unroll
    for (int i = 0; i < 2; i++)
        #pragma unroll
        for (int j = 0; j < 4; j++)
            wmma::store_matrix_sync(Zt + (mw * 32 + i * 16) * ZLD + nw * 64 + j * 16,
                                    c[i][j], ZLD, wmma::mem_row_major);
    __syncthreads();

    const float* Bi = s_ ? wB3 : hB3;
    int bb = tid >> 6, co = tid & 63;
    float bias = Bi[blockIdx.x * 64 + co];
    float y[32];
    const float* zb = Zt + (bb * 32) * ZLD;
    #pragma unroll
    for (int t = 0; t < 32; t++) {
        float z = zb[t * ZLD + co * 2] + bias;
        if (t > 0) z += zb[(t - 1) * ZLD + co * 2 + 1];
        y[t] = tanhf(z);
    }
    __syncthreads();
    float* yb = Zt + 128 * ZLD;
    #pragma unroll
    for (int t = 0; t < 32; t++) yb[(bb * 64 + co) * 36 + t] = y[t];
    __syncthreads();
    #pragma unroll
    for (int b2 = 0; b2 < 4; b2++) {
        float* o = g_o3 + s_ * (256 * 512 * 32)
                 + (((blockIdx.y * 4 + b2) * 512) + blockIdx.x * 64) * 32;
        for (int i = tid; i < 2048; i += 256)
            o[i] = yb[(b2 * 64 + (i >> 5)) * 36 + (i & 31)];
    }
}

// ---------------------------------------------------------------------------
// Stage 5: out[b,ch,y,x] = sum_r lrelu(BN(craw))*coef * h * w.
// grid 512 (b x y-half), 512 threads.
// ---------------------------------------------------------------------------
__global__ void __launch_bounds__(512)
k_final(const float* __restrict__ coef, float* __restrict__ out) {
    int b = blockIdx.x >> 1, yh = (blockIdx.x & 1) * 16;
    int tid = threadIdx.x;
    int y = yh + (tid >> 5), x = tid & 31;
    __shared__ float shh[32 * 32], shw[32 * 32], shc[96];
    float a0 = 0.f, a1 = 0.f, a2 = 0.f;
    int ri = tid >> 5, rp = tid & 31;
    for (int r0 = 0; r0 < 512; r0 += 32) {
        shh[tid]       = g_o3[                 (b * 512 + r0 + ri) * 32 + rp];
        shh[tid + 512] = g_o3[                 (b * 512 + r0 + 16 + ri) * 32 + rp];
        shw[tid]       = g_o3[256 * 512 * 32 + (b * 512 + r0 + ri) * 32 + rp];
        shw[tid + 512] = g_o3[256 * 512 * 32 + (b * 512 + r0 + 16 + ri) * 32 + rp];
        if (tid < 96) {
            int rr = tid / 3, c3 = tid % 3;
            int co = r0 + rr;
            float v = g_craw[b * 1536 + co * 3 + c3] * g_sc1c[co] + g_sh1c[co];
            v = v >= 0.f ? v : 0.2f * v;
            shc[tid] = v * coef[co];
        }
        __syncthreads();
        #pragma unroll
        for (int i = 0; i < 32; i++) {
            float p = shh[i * 32 + y] * shw[i * 32 + x];
            a0 += shc[i * 3 + 0] * p;
            a1 += shc[i * 3 + 1] * p;
            a2 += shc[i * 3 + 2] * p;
        }
        __syncthreads();
    }
    out[((b * 3 + 0) * 32 + y) * 32 + x] = a0;
    out[((b * 3 + 1) * 32 + y) * 32 + x] = a1;
    out[((b * 3 + 2) * 32 + y) * 32 + x] = a2;
}

// ---------------------------------------------------------------------------
extern "C" void kernel_launch(void* const* d_in, const int* in_sizes, int n_in,
                              void* d_out, int out_size) {
    const float* noise  = (const float*)d_in[0];
    const int*   label  = (const int*)  d_in[1];
    const float* lin_w  = (const float*)d_in[2];
    const float* lin_b  = (const float*)d_in[3];
    const float* bn0_g  = (const float*)d_in[4];
    const float* bn0_b  = (const float*)d_in[5];
    const float* emb    = (const float*)d_in[6];
    const float* c_w1   = (const float*)d_in[7];
    const float* c_b1   = (const float*)d_in[8];
    const float* c_g1   = (const float*)d_in[9];
    const float* c_be1  = (const float*)d_in[10];
    const float* h_w1   = (const float*)d_in[11];
    const float* h_b1   = (const float*)d_in[12];
    const float* h_g1   = (const float*)d_in[13];
    const float* h_be1  = (const float*)d_in[14];
    const float* h_w2   = (const float*)d_in[15];
    const float* h_b2   = (const float*)d_in[16];
    const float* h_g2   = (const float*)d_in[17];
    const float* h_be2  = (const float*)d_in[18];
    const float* h_w3   = (const float*)d_in[19];
    const float* h_b3   = (const float*)d_in[20];
    const float* w_w1   = (const float*)d_in[21];
    const float* w_b1   = (const float*)d_in[22];
    const float* w_g1   = (const float*)d_in[23];
    const float* w_be1  = (const float*)d_in[24];
    const float* w_w2   = (const float*)d_in[25];
    const float* w_b2   = (const float*)d_in[26];
    const float* w_g2   = (const float*)d_in[27];
    const float* w_be2  = (const float*)d_in[28];
    const float* w_w3   = (const float*)d_in[29];
    const float* w_b3   = (const float*)d_in[30];
    const float* coef   = (const float*)d_in[31];
    float* out = (float*)d_out;

    cudaFuncSetAttribute(k_gemm1,  cudaFuncAttributeMaxDynamicSharedMemorySize, SM_G16_B);
    cudaFuncSetAttribute(k_gemm16, cudaFuncAttributeMaxDynamicSharedMemorySize, SM_G16_B);
    cudaFuncSetAttribute(k_gemm2,  cudaFuncAttributeMaxDynamicSharedMemorySize, SM_G2_B);

    k_wprep  <<<11798, 256>>>(c_w1, h_w1, w_w1, c_b1, h_b1, w_b1,
                              h_w2, w_w2, h_w3, w_w3);
    k_latent <<<256,  256>>>(noise, label, lin_w, lin_b, bn0_g, bn0_b, emb);
    k_gemm1  <<<dim3(44, 2), 256, SM_G16_B>>>();
    k_bnstat1<<<12,   256>>>(c_g1, c_be1, h_g1, h_be1, w_g1, w_be1);
    k_gemm16 <<<dim3(32, 32, 2), 256, SM_G16_B>>>(h_b2, w_b2);
    k_bnstat <<<16,   256>>>(h_g2, h_be2, w_g2, w_be2);
    k_gemm2  <<<dim3(8, 64, 2), 256, SM_G2_B>>>(h_b3, w_b3);
    k_final  <<<512,  512>>>(coef, out);
}

// round 11
// speedup vs baseline: 1.1253x; 1.1253x over previous
#include <cuda_runtime.h>
#include <cuda_bf16.h>
#include <mma.h>
#include <math.h>

using namespace nvcuda;
typedef __nv_bfloat16 bf16;

// ---------------------------------------------------------------------------
// B=256, RANK=512, R4=128, R2=256
// conv1   GEMM: Y[b][n]              = latent @ W1cat  M=256  N=5632 K=256
// convT16 GEMM: Z[(b*16+s2)][(co,k)] = X2 @ W2         M=4096 N=4096 K=128
// convT2  GEMM: Z[(b*32+t)][(co,k)]  = X3 @ W3         M=8192 N=1024 K=256
// All bf16x3 (hi*hi + hi*lo + lo*hi, fp32 accumulate).
// ---------------------------------------------------------------------------

__device__ __align__(16) bf16 g_lathi[256 * 256];      // [b][ci]
__device__ __align__(16) bf16 g_latlo[256 * 256];
__device__ __align__(16) bf16 g_w1hi[256 * 5632];      // [ci][n]  c|h|w concat
__device__ __align__(16) bf16 g_w1lo[256 * 5632];
__device__ float g_bias1[5632];
__device__ float g_craw[256 * 1536];                   // conv1 c raw (bias incl)
__device__ float g_x2raw[2][4096 * 128];               // [(b,s2)][ci] raw
__device__ float g_p1sum[4][5632];
__device__ float g_p1sq [4][5632];
__device__ float g_sc1c[512], g_sh1c[512];
__device__ float g_sc1[2 * 128], g_sh1[2 * 128];       // h/w BN1 per ci
__device__ __align__(16) bf16 g_w2hi[2][128 * 4096];
__device__ __align__(16) bf16 g_w2lo[2][128 * 4096];
__device__ __align__(16) bf16 g_w3hi[2][256 * 1024];
__device__ __align__(16) bf16 g_w3lo[2][256 * 1024];
__device__ float g_y2t[2][8192 * 256];                 // raw conv2 out, gemm2-A layout
__device__ float g_psum[2 * 256 * 256];
__device__ float g_psq [2 * 256 * 256];
__device__ float g_sc[2 * 256];
__device__ float g_sh[2 * 256];
__device__ float g_o3[2 * 256 * 512 * 32];             // [s][b][r][32]

__device__ __forceinline__ void bf16split(float x, bf16& h, bf16& l) {
    h = __float2bfloat16(x);
    l = __float2bfloat16(x - __bfloat162float(h));
}

constexpr int ALD = 40;
constexpr int BLD = 136;
constexpr int ZLD = 132;
constexpr int A_ELEMS = 128 * ALD;
constexpr int B_ELEMS = 32 * BLD;
constexpr int SM_G16_B = 128 * ZLD * 4;                    // 67584
constexpr int SM_G2_B  = 128 * ZLD * 4 + 256 * 36 * 4;     // 104448

__device__ __forceinline__ void reduce2_256(float& s, float& ss) {
    __shared__ float rs[8], rss[8];
    #pragma unroll
    for (int o = 16; o > 0; o >>= 1) {
        s  += __shfl_down_sync(0xffffffffu, s,  o);
        ss += __shfl_down_sync(0xffffffffu, ss, o);
    }
    int wid = threadIdx.x >> 5, lane = threadIdx.x & 31;
    if (lane == 0) { rs[wid] = s; rss[wid] = ss; }
    __syncthreads();
    if (threadIdx.x < 32) {
        float a = lane < 8 ? rs[lane] : 0.f;
        float b = lane < 8 ? rss[lane] : 0.f;
        #pragma unroll
        for (int o = 4; o > 0; o >>= 1) {
            a += __shfl_down_sync(0xffffffffu, a, o);
            b += __shfl_down_sync(0xffffffffu, b, o);
        }
        if (lane == 0) { rs[0] = a; rss[0] = b; }
    }
    __syncthreads();
    s = rs[0]; ss = rss[0];
}

// ---------------------------------------------------------------------------
// bf16x3 128x128 block GEMM core (A/B bf16 in gmem). Single-buffered —
// inter-block overlap hides chunk latency; no prefetch register pressure.
// ---------------------------------------------------------------------------
template<int KTOT>
__device__ __forceinline__ void gemm_bf16x3(
    const bf16* __restrict__ Ahi, const bf16* __restrict__ Alo,
    const bf16* __restrict__ Bhi, const bf16* __restrict__ Blo,
    int m0, int n0, int ldb, char* smraw, float* Zt)
{
    bf16* sAh = (bf16*)smraw;
    bf16* sAl = sAh + A_ELEMS;
    bf16* sBh = sAl + A_ELEMS;
    bf16* sBl = sBh + B_ELEMS;
    int tid = threadIdx.x, w = tid >> 5;
    int mw = w >> 1, nw = w & 1;

    wmma::fragment<wmma::accumulator, 16, 16, 16, float> c[2][4];
    #pragma unroll
    for (int i = 0; i < 2; i++)
        #pragma unroll
        for (int j = 0; j < 4; j++) wmma::fill_fragment(c[i][j], 0.f);

    for (int kc = 0; kc < KTOT; kc += 32) {
        __syncthreads();
        #pragma unroll
        for (int r = 0; r < 2; r++) {
            int idx = tid + 256 * r;
            int row = idx >> 2, seg = (idx & 3) * 8;
            *(uint4*)(sAh + row * ALD + seg) =
                *(const uint4*)(Ahi + (size_t)(m0 + row) * KTOT + kc + seg);
            *(uint4*)(sAl + row * ALD + seg) =
                *(const uint4*)(Alo + (size_t)(m0 + row) * KTOT + kc + seg);
        }
        #pragma unroll
        for (int r = 0; r < 2; r++) {
            int idx = tid + 256 * r;
            int row = idx >> 4, seg = (idx & 15) * 8;
            *(uint4*)(sBh + row * BLD + seg) =
                *(const uint4*)(Bhi + (size_t)(kc + row) * ldb + n0 + seg);
            *(uint4*)(sBl + row * BLD + seg) =
                *(const uint4*)(Blo + (size_t)(kc + row) * ldb + n0 + seg);
        }
        __syncthreads();
        #pragma unroll
        for (int k0 = 0; k0 < 32; k0 += 16) {
            wmma::fragment<wmma::matrix_a, 16, 16, 16, bf16, wmma::row_major> ah[2], al[2];
            #pragma unroll
            for (int i = 0; i < 2; i++) {
                wmma::load_matrix_sync(ah[i], sAh + (mw * 32 + i * 16) * ALD + k0, ALD);
                wmma::load_matrix_sync(al[i], sAl + (mw * 32 + i * 16) * ALD + k0, ALD);
            }
            #pragma unroll
            for (int j = 0; j < 4; j++) {
                wmma::fragment<wmma::matrix_b, 16, 16, 16, bf16, wmma::row_major> bh, bl;
                wmma::load_matrix_sync(bh, sBh + k0 * BLD + nw * 64 + j * 16, BLD);
                wmma::load_matrix_sync(bl, sBl + k0 * BLD + nw * 64 + j * 16, BLD);
                #pragma unroll
                for (int i = 0; i < 2; i++) {
                    wmma::mma_sync(c[i][j], ah[i], bh, c[i][j]);
                    wmma::mma_sync(c[i][j], ah[i], bl, c[i][j]);
                    wmma::mma_sync(c[i][j], al[i], bh, c[i][j]);
                }
            }
        }
    }
    __syncthreads();
    #pragma unroll
    for (int i = 0; i < 2; i++)
        #pragma unroll
        for (int j = 0; j < 4; j++)
            wmma::store_matrix_sync(Zt + (mw * 32 + i * 16) * ZLD + nw * 64 + j * 16,
                                    c[i][j], ZLD, wmma::mem_row_major);
    __syncthreads();
}

// ---------------------------------------------------------------------------
// Stage 0: ALL weight prep in one launch. grid 11798 x 256.
// ---------------------------------------------------------------------------
__global__ void k_wprep(const float* __restrict__ cW1, const float* __restrict__ hW1,
                        const float* __restrict__ wW1,
                        const float* __restrict__ cB,  const float* __restrict__ hB,
                        const float* __restrict__ wB,
                        const float* __restrict__ hW2, const float* __restrict__ wW2,
                        const float* __restrict__ hW3, const float* __restrict__ wW3) {
    int blk = blockIdx.x, tid = threadIdx.x;
    if (blk < 5632) {
        int i = blk * 256 + tid;
        int ci = i / 5632, n = i % 5632;
        float x;
        if (n < 1536)      x = cW1[ci * 1536 + n];
        else if (n < 3584) x = hW1[ci * 2048 + n - 1536];
        else               x = wW1[ci * 2048 + n - 3584];
        bf16 h, l; bf16split(x, h, l);
        g_w1hi[i] = h; g_w1lo[i] = l;
    } else if (blk < 9728) {
        int i = (blk - 5632) * 256 + tid;
        int s_ = i >= 524288;
        int j = i - s_ * 524288;
        bf16 h, l; bf16split((s_ ? wW2 : hW2)[j], h, l);
        g_w2hi[s_][j] = h; g_w2lo[s_][j] = l;
    } else if (blk < 11776) {
        int i = (blk - 9728) * 256 + tid;
        int s_ = i >= 262144;
        int j = i - s_ * 262144;
        bf16 h, l; bf16split((s_ ? wW3 : hW3)[j], h, l);
        g_w3hi[s_][j] = h; g_w3lo[s_][j] = l;
    } else {
        int n = (blk - 11776) * 256 + tid;
        if (n < 5632) {
            float v;
            if (n < 1536)      v = cB[n / 3];
            else if (n < 3584) v = hB[(n - 1536) >> 4];
            else               v = wB[(n - 3584) >> 4];
            g_bias1[n] = v;
        }
    }
}

// ---------------------------------------------------------------------------
// Stage 1: latent row b -> bf16 hi/lo [b][ci].
// ---------------------------------------------------------------------------
__global__ void k_latent(const float* __restrict__ noise, const int* __restrict__ label,
                         const float* __restrict__ lin_w, const float* __restrict__ lin_b,
                         const float* __restrict__ g,     const float* __restrict__ be,
                         const float* __restrict__ emb) {
    int j = blockIdx.x, b = threadIdx.x;
    if (j >= 128) {
        int jj = j - 128;
        bf16 h, l;
        bf16split(emb[label[b] * 128 + jj], h, l);
        g_lathi[b * 256 + 128 + jj] = h;
        g_latlo[b * 256 + 128 + jj] = l;
        return;
    }
    __shared__ float wsm[100];
    if (b < 100) wsm[b] = lin_w[j * 100 + b];
    __syncthreads();
    float acc = lin_b[j];
    const float* nb = noise + b * 100;
    #pragma unroll 4
    for (int i = 0; i < 100; i++) acc += nb[i] * wsm[i];
    float s = acc, ss = acc * acc;
    reduce2_256(s, ss);
    float mean = s * (1.f / 256.f);
    float var  = ss * (1.f / 256.f) - mean * mean;
    float sc   = g[j] * rsqrtf(var + 1e-5f);
    float v    = (acc - mean) * sc + be[j];
    v = v >= 0.f ? v : 0.01f * v;
    bf16 h, l;
    bf16split(v, h, l);
    g_lathi[b * 256 + j] = h;
    g_latlo[b * 256 + j] = l;
}

// ---------------------------------------------------------------------------
// Stage 2: conv1 GEMM. grid (44, 2). Epilogue: +bias, raw out, col partials.
// ---------------------------------------------------------------------------
__global__ void __launch_bounds__(256)
k_gemm1() {
    extern __shared__ char smraw[];
    float* Zt = (float*)smraw;
    int n0 = blockIdx.x * 128, m0 = blockIdx.y * 128;
    gemm_bf16x3<256>(g_lathi, g_latlo, g_w1hi, g_w1lo, m0, n0, 5632, smraw, Zt);

    __shared__ float sbias[128];
    int tid = threadIdx.x;
    if (tid < 128) sbias[tid] = g_bias1[n0 + tid];
    __syncthreads();

    if (n0 < 1536) {
        for (int r = 0; r < 64; r++) {
            int i = tid + 256 * r;
            int row = i >> 7, col = i & 127;
            float y = Zt[row * ZLD + col] + sbias[col];
            Zt[row * ZLD + col] = y;
            g_craw[(m0 + row) * 1536 + n0 + col] = y;
        }
    } else {
        int s_ = n0 >= 3584;
        int cobase = (n0 - (s_ ? 3584 : 1536)) >> 4;
        for (int r = 0; r < 64; r++) {
            int i = tid + 256 * r;
            int row = i >> 7, col = i & 127;
            float y = Zt[row * ZLD + col] + sbias[col];
            Zt[row * ZLD + col] = y;
            int k = col & 15, co = cobase + (col >> 4);
            g_x2raw[s_][((m0 + row) * 16 + k) * 128 + co] = y;
        }
    }
    __syncthreads();
    int col = tid & 127, half = tid >> 7;
    float sum = 0.f, sq = 0.f;
    for (int r = 0; r < 64; r++) {
        float y = Zt[(half * 64 + r) * ZLD + col];
        sum += y;
        sq  += y * y;
    }
    int p = blockIdx.y * 2 + half;
    g_p1sum[p][n0 + col] = sum;
    g_p1sq [p][n0 + col] = sq;
}

// ---------------------------------------------------------------------------
// Stage 2b: conv1 BN stats. grid 12 x 256 — one (co, part) per thread,
// width-4 shfl fold.
// ---------------------------------------------------------------------------
__global__ void __launch_bounds__(256)
k_bnstat1(const float* __restrict__ cG, const float* __restrict__ cBe,
          const float* __restrict__ hG, const float* __restrict__ hBe,
          const float* __restrict__ wG, const float* __restrict__ wBe) {
    int gid = blockIdx.x * 256 + threadIdx.x;
    if (gid < 2048) {                                  // c branch: 512 co x 4 p
        int co = gid >> 2, p = gid & 3;
        const float* ps = g_p1sum[p] + co * 3;
        const float* pq = g_p1sq [p] + co * 3;
        float sum = ps[0] + ps[1] + ps[2];
        float sq  = pq[0] + pq[1] + pq[2];
        sum += __shfl_down_sync(0xffffffffu, sum, 2, 4);
        sum += __shfl_down_sync(0xffffffffu, sum, 1, 4);
        sq  += __shfl_down_sync(0xffffffffu, sq,  2, 4);
        sq  += __shfl_down_sync(0xffffffffu, sq,  1, 4);
        if (p == 0) {
            const float invN = 1.f / 768.f;
            float mean = sum * invN, var = sq * invN - mean * mean;
            float sc = cG[co] * rsqrtf(var + 1e-5f);
            g_sc1c[co] = sc;
            g_sh1c[co] = cBe[co] - mean * sc;
        }
    } else {                                           // h/w: 256 co x 4 p
        int id = gid - 2048;
        int coidx = id >> 2, p = id & 3;
        int s_ = coidx >> 7, co = coidx & 127;
        int base = 1536 + s_ * 2048 + co * 16;
        const float4* ps = (const float4*)(g_p1sum[p] + base);
        const float4* pq = (const float4*)(g_p1sq [p] + base);
        float sum = 0.f, sq = 0.f;
        #pragma unroll
        for (int i = 0; i < 4; i++) {
            float4 v = ps[i]; sum += v.x + v.y + v.z + v.w;
            float4 q = pq[i]; sq  += q.x + q.y + q.z + q.w;
        }
        sum += __shfl_down_sync(0xffffffffu, sum, 2, 4);
        sum += __shfl_down_sync(0xffffffffu, sum, 1, 4);
        sq  += __shfl_down_sync(0xffffffffu, sq,  2, 4);
        sq  += __shfl_down_sync(0xffffffffu, sq,  1, 4);
        if (p == 0) {
            const float* G  = s_ ? wG  : hG;
            const float* Be = s_ ? wBe : hBe;
            const float invN = 1.f / 4096.f;
            float mean = sum * invN, var = sq * invN - mean * mean;
            float sc = G[co] * rsqrtf(var + 1e-5f);
            g_sc1[s_ * 128 + co] = sc;
            g_sh1[s_ * 128 + co] = Be[co] - mean * sc;
        }
    }
}

// ---------------------------------------------------------------------------
// Stage 3: convT16 GEMM, BN1 fused in A loader; epilogue folds + writes raw
// y2 in gemm2-A layout + BN2 partials. grid (32,32,2), 256 threads.
// ---------------------------------------------------------------------------
__global__ void __launch_bounds__(256)
k_gemm16(const float* __restrict__ hB2, const float* __restrict__ wB2) {
    extern __shared__ char smraw[];
    float* Zt = (float*)smraw;
    bf16* sAh = (bf16*)smraw;
    bf16* sAl = sAh + A_ELEMS;
    bf16* sBh = sAl + A_ELEMS;
    bf16* sBl = sBh + B_ELEMS;
    __shared__ float ssc[128], ssh[128];
    int s_ = blockIdx.z;
    int m0 = blockIdx.y * 128, n0 = blockIdx.x * 128;
    int tid = threadIdx.x, w = tid >> 5, mw = w >> 1, nw = w & 1;
    if (tid < 128) {
        ssc[tid] = g_sc1[s_ * 128 + tid];
        ssh[tid] = g_sh1[s_ * 128 + tid];
    }
    const bf16* Bhi = g_w2hi[s_];
    const bf16* Blo = g_w2lo[s_];
    const float* Xr = g_x2raw[s_];

    wmma::fragment<wmma::accumulator, 16, 16, 16, float> c[2][4];
    #pragma unroll
    for (int i = 0; i < 2; i++)
        #pragma unroll
        for (int j = 0; j < 4; j++) wmma::fill_fragment(c[i][j], 0.f);

    for (int kc = 0; kc < 128; kc += 32) {
        __syncthreads();
        #pragma unroll
        for (int r = 0; r < 2; r++) {                     // A: BN + lrelu + split
            int idx = tid + 256 * r;
            int row = idx >> 2, seg = (idx & 3) * 8;
            const float* src = Xr + (size_t)(m0 + row) * 128 + kc + seg;
            float4 fa = *(const float4*)src;
            float4 fb = *(const float4*)(src + 4);
            float vs[8] = {fa.x, fa.y, fa.z, fa.w, fb.x, fb.y, fb.z, fb.w};
            __align__(16) bf16 hs[8], ls[8];
            #pragma unroll
            for (int j = 0; j < 8; j++) {
                int ci = kc + seg + j;
                float y = vs[j] * ssc[ci] + ssh[ci];
                y = y >= 0.f ? y : 0.2f * y;
                bf16split(y, hs[j], ls[j]);
            }
            *(uint4*)(sAh + row * ALD + seg) = *(uint4*)hs;
            *(uint4*)(sAl + row * ALD + seg) = *(uint4*)ls;
        }
        #pragma unroll
        for (int r = 0; r < 2; r++) {                     // B: bf16 direct
            int idx = tid + 256 * r;
            int row = idx >> 4, seg = (idx & 15) * 8;
            *(uint4*)(sBh + row * BLD + seg) =
                *(const uint4*)(Bhi + (size_t)(kc + row) * 4096 + n0 + seg);
            *(uint4*)(sBl + row * BLD + seg) =
                *(const uint4*)(Blo + (size_t)(kc + row) * 4096 + n0 + seg);
        }
        __syncthreads();
        #pragma unroll
        for (int k0 = 0; k0 < 32; k0 += 16) {
            wmma::fragment<wmma::matrix_a, 16, 16, 16, bf16, wmma::row_major> ah[2], al[2];
            #pragma unroll
            for (int i = 0; i < 2; i++) {
                wmma::load_matrix_sync(ah[i], sAh + (mw * 32 + i * 16) * ALD + k0, ALD);
                wmma::load_matrix_sync(al[i], sAl + (mw * 32 + i * 16) * ALD + k0, ALD);
            }
            #pragma unroll
            for (int j = 0; j < 4; j++) {
                wmma::fragment<wmma::matrix_b, 16, 16, 16, bf16, wmma::row_major> bh, bl;
                wmma::load_matrix_sync(bh, sBh + k0 * BLD + nw * 64 + j * 16, BLD);
                wmma::load_matrix_sync(bl, sBl + k0 * BLD + nw * 64 + j * 16, BLD);
                #pragma unroll
                for (int i = 0; i < 2; i++) {
                    wmma::mma_sync(c[i][j], ah[i], bh, c[i][j]);
                    wmma::mma_sync(c[i][j], ah[i], bl, c[i][j]);
                    wmma::mma_sync(c[i][j], al[i], bh, c[i][j]);
                }
            }
        }
    }
    __syncthreads();
    #pragma unroll
    for (int i = 0; i < 2; i++)
        #pragma unroll
        for (int j = 0; j < 4; j++)
            wmma::store_matrix_sync(Zt + (mw * 32 + i * 16) * ZLD + nw * 64 + j * 16,
                                    c[i][j], ZLD, wmma::mem_row_major);
    __syncthreads();

    // fold epilogue -> g_y2t[(b*32+t)][co]
    const float* Bi = s_ ? wB2 : hB2;
    int pair = tid >> 2, sub = tid & 3;
    int bb = pair >> 3, cc = pair & 7;
    int b  = blockIdx.y * 8 + bb;
    int co = blockIdx.x * 8 + cc;
    float bias = Bi[co];
    float psum = 0.f, psq = 0.f;
    float* yo = g_y2t[s_] + (size_t)b * 32 * 256 + co;
    const float* zrow = Zt + (bb * 16) * ZLD + cc * 16;
    #pragma unroll
    for (int ti = 0; ti < 8; ti++) {
        int t = sub + ti * 4;
        float v = 0.f;
        if (t < 31) {
            #pragma unroll
            for (int k = 0; k < 16; k++) {
                int s2 = t - k;
                if (s2 >= 0 && s2 < 16) v += zrow[s2 * ZLD + k];
            }
            v += bias;
        }
        yo[t * 256] = v;
        psum += v;
        psq  += v * v;
    }
    psum += __shfl_down_sync(0xffffffffu, psum, 2, 4);
    psum += __shfl_down_sync(0xffffffffu, psum, 1, 4);
    psq  += __shfl_down_sync(0xffffffffu, psq, 2, 4);
    psq  += __shfl_down_sync(0xffffffffu, psq, 1, 4);
    if (sub == 0) {
        g_psum[s_ * 65536 + b * 256 + co] = psum;
        g_psq [s_ * 65536 + b * 256 + co] = psq;
    }
}

// ---------------------------------------------------------------------------
// Stage 3b: BN2 partial reduce. grid 16 x 256.
// ---------------------------------------------------------------------------
__global__ void __launch_bounds__(256)
k_bnstat(const float* __restrict__ hG, const float* __restrict__ hBe,
         const float* __restrict__ wG, const float* __restrict__ wBe) {
    int s_  = blockIdx.x >> 3;
    int co0 = (blockIdx.x & 7) * 32;
    int col = threadIdx.x & 31, bp = threadIdx.x >> 5;
    const float* ps = g_psum + s_ * 65536 + co0 + col;
    const float* pq = g_psq  + s_ * 65536 + co0 + col;
    float sum = 0.f, sq = 0.f;
    #pragma unroll 8
    for (int i = 0; i < 32; i++) {
        int b = bp + 8 * i;
        sum += ps[b * 256];
        sq  += pq[b * 256];
    }
    __shared__ float ssum[8][32], ssq[8][32];
    ssum[bp][col] = sum; ssq[bp][col] = sq;
    __syncthreads();
    if (bp == 0) {
        #pragma unroll
        for (int r = 1; r < 8; r++) { sum += ssum[r][col]; sq += ssq[r][col]; }
        const float* G  = s_ ? wG  : hG;
        const float* Be = s_ ? wBe : hBe;
        int co = co0 + col;
        const float invN = 1.f / (256.f * 31.f);
        float mean = sum * invN, var = sq * invN - mean * mean;
        float sc = G[co] * rsqrtf(var + 1e-5f);
        g_sc[s_ * 256 + co] = sc;
        g_sh[s_ * 256 + co] = Be[co] - mean * sc;
    }
}

// ---------------------------------------------------------------------------
// Stage 4: convT2 GEMM, BN2+lrelu+split fused in A loader (t==31 rows zero);
// epilogue folds k=2 + tanh + coalesced store. grid (8,64,2), 256 threads.
// ---------------------------------------------------------------------------
__global__ void __launch_bounds__(256)
k_gemm2(const float* __restrict__ hB3, const float* __restrict__ wB3) {
    extern __shared__ char smraw[];
    float* Zt = (float*)smraw;
    bf16* sAh = (bf16*)smraw;
    bf16* sAl = sAh + A_ELEMS;
    bf16* sBh = sAl + A_ELEMS;
    bf16* sBl = sBh + B_ELEMS;
    __shared__ float ssc[256], ssh[256];
    int s_ = blockIdx.z;
    int m0 = blockIdx.y * 128, n0 = blockIdx.x * 128;
    int tid = threadIdx.x, w = tid >> 5, mw = w >> 1, nw = w & 1;
    ssc[tid] = g_sc[s_ * 256 + tid];
    ssh[tid] = g_sh[s_ * 256 + tid];
    const bf16* Bhi = g_w3hi[s_];
    const bf16* Blo = g_w3lo[s_];
    const float* Xr = g_y2t[s_];

    wmma::fragment<wmma::accumulator, 16, 16, 16, float> c[2][4];
    #pragma unroll
    for (int i = 0; i < 2; i++)
        #pragma unroll
        for (int j = 0; j < 4; j++) wmma::fill_fragment(c[i][j], 0.f);

    for (int kc = 0; kc < 256; kc += 32) {
        __syncthreads();
        #pragma unroll
        for (int r = 0; r < 2; r++) {
            int idx = tid + 256 * r;
            int row = idx >> 2, seg = (idx & 3) * 8;
            const float* src = Xr + (size_t)(m0 + row) * 256 + kc + seg;
            float4 fa = *(const float4*)src;
            float4 fb = *(const float4*)(src + 4);
            float vs[8] = {fa.x, fa.y, fa.z, fa.w, fb.x, fb.y, fb.z, fb.w};
            bool zero = (row & 31) == 31;              // t==31 rows are zero input
            __align__(16) bf16 hs[8], ls[8];
            #pragma unroll
            for (int j = 0; j < 8; j++) {
                int ci = kc + seg + j;
                float y = vs[j] * ssc[ci] + ssh[ci];
                y = y >= 0.f ? y : 0.2f * y;
                if (zero) y = 0.f;
                bf16split(y, hs[j], ls[j]);
            }
            *(uint4*)(sAh + row * ALD + seg) = *(uint4*)hs;
            *(uint4*)(sAl + row * ALD + seg) = *(uint4*)ls;
        }
        #pragma unroll
        for (int r = 0; r < 2; r++) {
            int idx = tid + 256 * r;
            int row = idx >> 4, seg = (idx & 15) * 8;
            *(uint4*)(sBh + row * BLD + seg) =
                *(const uint4*)(Bhi + (size_t)(kc + row) * 1024 + n0 + seg);
            *(uint4*)(sBl + row * BLD + seg) =
                *(const uint4*)(Blo + (size_t)(kc + row) * 1024 + n0 + seg);
        }
        __syncthreads();
        #pragma unroll
        for (int k0 = 0; k0 < 32; k0 += 16) {
            wmma::fragment<wmma::matrix_a, 16, 16, 16, bf16, wmma::row_major> ah[2], al[2];
            #pragma unroll
            for (int i = 0; i < 2; i++) {
                wmma::load_matrix_sync(ah[i], sAh + (mw * 32 + i * 16) * ALD + k0, ALD);
                wmma::load_matrix_sync(al[i], sAl + (mw * 32 + i * 16) * ALD + k0, ALD);
            }
            #pragma unroll
            for (int j = 0; j < 4; j++) {
                wmma::fragment<wmma::matrix_b, 16, 16, 16, bf16, wmma::row_major> bh, bl;
                wmma::load_matrix_sync(bh, sBh + k0 * BLD + nw * 64 + j * 16, BLD);
                wmma::load_matrix_sync(bl, sBl + k0 * BLD + nw * 64 + j * 16, BLD);
                #pragma unroll
                for (int i = 0; i < 2; i++) {
                    wmma::mma_sync(c[i][j], ah[i], bh, c[i][j]);
                    wmma::mma_sync(c[i][j], ah[i], bl, c[i][j]);
                    wmma::mma_sync(c[i][j], al[i], bh, c[i][j]);
                }
            }
        }
    }
    __syncthreads();
    #pragma unroll
    for (int i = 0; i < 2; i++)
        #pragma unroll
        for (int j = 0; j < 4; j++)
            wmma::store_matrix_sync(Zt + (mw * 32 + i * 16) * ZLD + nw * 64 + j * 16,
                                    c[i][j], ZLD, wmma::mem_row_major);
    __syncthreads();

    const float* Bi = s_ ? wB3 : hB3;
    int bb = tid >> 6, co = tid & 63;
    float bias = Bi[blockIdx.x * 64 + co];
    float y[32];
    const float* zb = Zt + (bb * 32) * ZLD;
    #pragma unroll
    for (int t = 0; t < 32; t++) {
        float z = zb[t * ZLD + co * 2] + bias;
        if (t > 0) z += zb[(t - 1) * ZLD + co * 2 + 1];
        y[t] = tanhf(z);
    }
    __syncthreads();
    float* yb = Zt + 128 * ZLD;
    #pragma unroll
    for (int t = 0; t < 32; t++) yb[(bb * 64 + co) * 36 + t] = y[t];
    __syncthreads();
    #pragma unroll
    for (int b2 = 0; b2 < 4; b2++) {
        float* o = g_o3 + s_ * (256 * 512 * 32)
                 + (((blockIdx.y * 4 + b2) * 512) + blockIdx.x * 64) * 32;
        for (int i = tid; i < 2048; i += 256)
            o[i] = yb[(b2 * 64 + (i >> 5)) * 36 + (i & 31)];
    }
}

// ---------------------------------------------------------------------------
// Stage 5: out[b,ch,y,x] = sum_r lrelu(BN(craw))*coef * h * w.
// grid 512 (b x y-half), 512 threads.
// ---------------------------------------------------------------------------
__global__ void __launch_bounds__(512)
k_final(const float* __restrict__ coef, float* __restrict__ out) {
    int b = blockIdx.x >> 1, yh = (blockIdx.x & 1) * 16;
    int tid = threadIdx.x;
    int y = yh + (tid >> 5), x = tid & 31;
    __shared__ float shh[32 * 32], shw[32 * 32], shc[96];
    float a0 = 0.f, a1 = 0.f, a2 = 0.f;
    int ri = tid >> 5, rp = tid & 31;
    for (int r0 = 0; r0 < 512; r0 += 32) {
        shh[tid]       = g_o3[                 (b * 512 + r0 + ri) * 32 + rp];
        shh[tid + 512] = g_o3[                 (b * 512 + r0 + 16 + ri) * 32 + rp];
        shw[tid]       = g_o3[256 * 512 * 32 + (b * 512 + r0 + ri) * 32 + rp];
        shw[tid + 512] = g_o3[256 * 512 * 32 + (b * 512 + r0 + 16 + ri) * 32 + rp];
        if (tid < 96) {
            int rr = tid / 3, c3 = tid % 3;
            int co = r0 + rr;
            float v = g_craw[b * 1536 + co * 3 + c3] * g_sc1c[co] + g_sh1c[co];
            v = v >= 0.f ? v : 0.2f * v;
            shc[tid] = v * coef[co];
        }
        __syncthreads();
        #pragma unroll
        for (int i = 0; i < 32; i++) {
            float p = shh[i * 32 + y] * shw[i * 32 + x];
            a0 += shc[i * 3 + 0] * p;
            a1 += shc[i * 3 + 1] * p;
            a2 += shc[i * 3 + 2] * p;
        }
        __syncthreads();
    }
    out[((b * 3 + 0) * 32 + y) * 32 + x] = a0;
    out[((b * 3 + 1) * 32 + y) * 32 + x] = a1;
    out[((b * 3 + 2) * 32 + y) * 32 + x] = a2;
}

// ---------------------------------------------------------------------------
extern "C" void kernel_launch(void* const* d_in, const int* in_sizes, int n_in,
                              void* d_out, int out_size) {
    const float* noise  = (const float*)d_in[0];
    const int*   label  = (const int*)  d_in[1];
    const float* lin_w  = (const float*)d_in[2];
    const float* lin_b  = (const float*)d_in[3];
    const float* bn0_g  = (const float*)d_in[4];
    const float* bn0_b  = (const float*)d_in[5];
    const float* emb    = (const float*)d_in[6];
    const float* c_w1   = (const float*)d_in[7];
    const float* c_b1   = (const float*)d_in[8];
    const float* c_g1   = (const float*)d_in[9];
    const float* c_be1  = (const float*)d_in[10];
    const float* h_w1   = (const float*)d_in[11];
    const float* h_b1   = (const float*)d_in[12];
    const float* h_g1   = (const float*)d_in[13];
    const float* h_be1  = (const float*)d_in[14];
    const float* h_w2   = (const float*)d_in[15];
    const float* h_b2   = (const float*)d_in[16];
    const float* h_g2   = (const float*)d_in[17];
    const float* h_be2  = (const float*)d_in[18];
    const float* h_w3   = (const float*)d_in[19];
    const float* h_b3   = (const float*)d_in[20];
    const float* w_w1   = (const float*)d_in[21];
    const float* w_b1   = (const float*)d_in[22];
    const float* w_g1   = (const float*)d_in[23];
    const float* w_be1  = (const float*)d_in[24];
    const float* w_w2   = (const float*)d_in[25];
    const float* w_b2   = (const float*)d_in[26];
    const float* w_g2   = (const float*)d_in[27];
    const float* w_be2  = (const float*)d_in[28];
    const float* w_w3   = (const float*)d_in[29];
    const float* w_b3   = (const float*)d_in[30];
    const float* coef   = (const float*)d_in[31];
    float* out = (float*)d_out;

    cudaFuncSetAttribute(k_gemm1,  cudaFuncAttributeMaxDynamicSharedMemorySize, SM_G16_B);
    cudaFuncSetAttribute(k_gemm16, cudaFuncAttributeMaxDynamicSharedMemorySize, SM_G16_B);
    cudaFuncSetAttribute(k_gemm2,  cudaFuncAttributeMaxDynamicSharedMemorySize, SM_G2_B);

    k_wprep  <<<11798, 256>>>(c_w1, h_w1, w_w1, c_b1, h_b1, w_b1,
                              h_w2, w_w2, h_w3, w_w3);
    k_latent <<<256,  256>>>(noise, label, lin_w, lin_b, bn0_g, bn0_b, emb);
    k_gemm1  <<<dim3(44, 2), 256, SM_G16_B>>>();
    k_bnstat1<<<12,   256>>>(c_g1, c_be1, h_g1, h_be1, w_g1, w_be1);
    k_gemm16 <<<dim3(32, 32, 2), 256, SM_G16_B>>>(h_b2, w_b2);
    k_bnstat <<<16,   256>>>(h_g2, h_be2, w_g2, w_be2);
    k_gemm2  <<<dim3(8, 64, 2), 256, SM_G2_B>>>(h_b3, w_b3);
    k_final  <<<512,  512>>>(coef, out);
}